// round 14
// baseline (speedup 1.0000x reference)
#include <cuda_runtime.h>
#include <cstdint>

// Problem constants: B=128, C=3, H=W=256, PROB=0.9, BRI=CON=SAT=0.2, CUT=0.25 -> CH=CW=64.
#define PROB_ 0.9f
static constexpr int B_     = 128;
static constexpr int H_     = 256;
static constexpr int W_     = 256;
static constexpr int CH_    = 64;
static constexpr int CW_    = 64;
static constexpr int PLANE  = H_ * W_;     // 65536 floats
static constexpr int PLANE4 = PLANE / 4;   // 16384 float4
static constexpr int NT     = 1024;        // threads per block
static constexpr int IT     = PLANE4 / NT; // 16 float4 per thread per plane

// ---------------------------------------------------------------------------
// One block = one batch, single wave (128 CTAs), no clusters, no SMEM tiles.
//
// KEY RESTRUCTURE: out_ch = A*x_f + D*g0_f + E_ch, where only E_ch depends on
// the plane means (A = s*b*c and D = (1-s)*b*c come straight from the input
// scalars). So:
//   Phase 1: read input (flipped, __ldcs last-use), accumulate channel sums,
//            AND immediately store y = fma(A, x, D*gray). Reads (DRAM) and
//            writes (L2 write-allocate; output fits in L2, drain is deferred
//            past kernel end) interleave in the same instruction stream ->
//            the read/write mixing that pure scheduling could never produce.
//   Phase 2: block-reduce sums -> means -> E_ch; each thread revisits exactly
//            the addresses IT stored (thread-local, no fence needed),
//            newest-first (L1/L2-hot): out = cut ? 0 : y + E_ch.
//
// Copy batches (apply_u >= PROB): single-pass streaming copy, no fixup.
// flip preserves plane means; sums over flipped loads cover the same set.
// ---------------------------------------------------------------------------
__global__ __launch_bounds__(NT) void batch_kernel(
    const float* __restrict__ img,
    const float* __restrict__ apply_u,
    const float* __restrict__ flip_u,
    const float* __restrict__ bri_u,
    const float* __restrict__ con_u,
    const float* __restrict__ sat_u,
    const int*   __restrict__ top_idx,
    const int*   __restrict__ left_idx,
    float* __restrict__ out)
{
    const int b   = blockIdx.x;
    const int tid = threadIdx.x;

    const float4* p0 = reinterpret_cast<const float4*>(img + (size_t)b * 3 * PLANE);
    const float4* p1 = p0 + PLANE4;
    const float4* p2 = p0 + 2 * PLANE4;
    float4* o0 = reinterpret_cast<float4*>(out + (size_t)b * 3 * PLANE);
    float4* o1 = o0 + PLANE4;
    float4* o2 = o0 + 2 * PLANE4;

    const bool apply = (__ldg(apply_u + b) < PROB_);

    if (!apply) {
        // Single-pass streaming copy (uniform per block).
#pragma unroll
        for (int i = 0; i < IT; i++) {
            const int idx = tid + i * NT;
            o0[idx] = __ldcs(p0 + idx);
            o1[idx] = __ldcs(p1 + idx);
            o2[idx] = __ldcs(p2 + idx);
        }
        return;
    }

    // Per-batch factors that do NOT need the mean.
    const float bv = 0.8f + 0.4f * __ldg(bri_u + b);
    const float cv = 0.8f + 0.4f * __ldg(con_u + b);
    const float sv = 0.8f + 0.4f * __ldg(sat_u + b);
    const float A  = sv * bv * cv;
    const float D  = (1.0f - sv) * bv * cv;

    const bool flip = (__ldg(flip_u + b) < 0.5f);

    // ---------------- Phase 1: read (DRAM) + sum + store y (L2) mixed ------
    float s0 = 0.0f, s1 = 0.0f, s2 = 0.0f;
#pragma unroll 8
    for (int i = 0; i < IT; i++) {
        const int idx = tid + i * NT;      // output float4 index in plane
        const int h   = idx >> 6;          // row
        const int wg  = idx & 63;          // output float4 column group
        const int sw  = flip ? (63 - wg) : wg;
        const int sidx = (h << 6) + sw;

        float4 r = __ldcs(p0 + sidx);      // last use of the input line
        float4 g = __ldcs(p1 + sidx);
        float4 c = __ldcs(p2 + sidx);

        // Sums are order-independent: summing the flipped set == plane sum.
        s0 += (r.x + r.y) + (r.z + r.w);
        s1 += (g.x + g.y) + (g.z + g.w);
        s2 += (c.x + c.y) + (c.z + c.w);

        if (flip) {
            float t;
            t = r.x; r.x = r.w; r.w = t;  t = r.y; r.y = r.z; r.z = t;
            t = g.x; g.x = g.w; g.w = t;  t = g.y; g.y = g.z; g.z = t;
            t = c.x; c.x = c.w; c.w = t;  t = c.y; c.y = c.z; c.z = t;
        }

        float4 gr;
        gr.x = (r.x + g.x + c.x) * (1.0f / 3.0f);
        gr.y = (r.y + g.y + c.y) * (1.0f / 3.0f);
        gr.z = (r.z + g.z + c.z) * (1.0f / 3.0f);
        gr.w = (r.w + g.w + c.w) * (1.0f / 3.0f);

        float4 yR, yG, yB;
        yR.x = fmaf(A, r.x, D * gr.x);  yR.y = fmaf(A, r.y, D * gr.y);
        yR.z = fmaf(A, r.z, D * gr.z);  yR.w = fmaf(A, r.w, D * gr.w);
        yG.x = fmaf(A, g.x, D * gr.x);  yG.y = fmaf(A, g.y, D * gr.y);
        yG.z = fmaf(A, g.z, D * gr.z);  yG.w = fmaf(A, g.w, D * gr.w);
        yB.x = fmaf(A, c.x, D * gr.x);  yB.y = fmaf(A, c.y, D * gr.y);
        yB.z = fmaf(A, c.z, D * gr.z);  yB.w = fmaf(A, c.w, D * gr.w);

        o0[idx] = yR;
        o1[idx] = yG;
        o2[idx] = yB;
    }

    // ---------------- Block reduce -> means -> E_ch -------------------------
#pragma unroll
    for (int o = 16; o > 0; o >>= 1) {
        s0 += __shfl_xor_sync(0xFFFFFFFFu, s0, o);
        s1 += __shfl_xor_sync(0xFFFFFFFFu, s1, o);
        s2 += __shfl_xor_sync(0xFFFFFFFFu, s2, o);
    }
    __shared__ float smW[3][32];
    __shared__ float smMean[3];
    const int wid = tid >> 5;
    if ((tid & 31) == 0) { smW[0][wid] = s0; smW[1][wid] = s1; smW[2][wid] = s2; }
    __syncthreads();
    if (tid < 32) {
        float a = smW[0][tid], d = smW[1][tid], e = smW[2][tid];
#pragma unroll
        for (int o = 16; o > 0; o >>= 1) {
            a += __shfl_xor_sync(0xFFFFFFFFu, a, o);
            d += __shfl_xor_sync(0xFFFFFFFFu, d, o);
            e += __shfl_xor_sync(0xFFFFFFFFu, e, o);
        }
        if (tid == 0) {
            const float inv = 1.0f / (float)PLANE;
            smMean[0] = a * inv; smMean[1] = d * inv; smMean[2] = e * inv;
        }
    }
    __syncthreads();

    const float M0 = smMean[0] * bv;
    const float M1 = smMean[1] * bv;
    const float M2 = smMean[2] * bv;
    const float Mbar = (M0 + M1 + M2) * (1.0f / 3.0f);

    const float k  = 1.0f - cv;
    const float os = 1.0f - sv;
    const float E0 = k * (sv * M0 + os * Mbar);
    const float E1 = k * (sv * M1 + os * Mbar);
    const float E2 = k * (sv * M2 + os * Mbar);

    const int t_ = __ldg(top_idx + b);
    const int l_ = __ldg(left_idx + b);

    // ---------------- Phase 2: fixup += E_ch, cutout (thread-local, L2-hot) --
    // Newest-first: the most recently stored lines are hottest in L1/L2.
#pragma unroll 8
    for (int i = IT - 1; i >= 0; i--) {
        const int idx = tid + i * NT;
        const int h   = idx >> 6;
        const int wg  = idx & 63;
        const int w0  = wg << 2;
        const bool row_in = (h >= t_) && (h < t_ + CH_);

        float4 yR = o0[idx];
        float4 yG = o1[idx];
        float4 yB = o2[idx];

        bool cut; int col;
        col = w0 + 0; cut = row_in && (col >= l_) && (col < l_ + CW_);
        yR.x = cut ? 0.0f : yR.x + E0;
        yG.x = cut ? 0.0f : yG.x + E1;
        yB.x = cut ? 0.0f : yB.x + E2;

        col = w0 + 1; cut = row_in && (col >= l_) && (col < l_ + CW_);
        yR.y = cut ? 0.0f : yR.y + E0;
        yG.y = cut ? 0.0f : yG.y + E1;
        yB.y = cut ? 0.0f : yB.y + E2;

        col = w0 + 2; cut = row_in && (col >= l_) && (col < l_ + CW_);
        yR.z = cut ? 0.0f : yR.z + E0;
        yG.z = cut ? 0.0f : yG.z + E1;
        yB.z = cut ? 0.0f : yB.z + E2;

        col = w0 + 3; cut = row_in && (col >= l_) && (col < l_ + CW_);
        yR.w = cut ? 0.0f : yR.w + E0;
        yG.w = cut ? 0.0f : yG.w + E1;
        yB.w = cut ? 0.0f : yB.w + E2;

        o0[idx] = yR;
        o1[idx] = yG;
        o2[idx] = yB;
    }
}

extern "C" void kernel_launch(void* const* d_in, const int* in_sizes, int n_in,
                              void* d_out, int out_size) {
    const float* images       = (const float*)d_in[0];
    const float* apply_u      = (const float*)d_in[1];
    const float* flip_u       = (const float*)d_in[2];
    const float* brightness_u = (const float*)d_in[3];
    const float* contrast_u   = (const float*)d_in[4];
    const float* saturation_u = (const float*)d_in[5];
    const int*   top_idx      = (const int*)d_in[6];
    const int*   left_idx     = (const int*)d_in[7];
    float* out = (float*)d_out;

    batch_kernel<<<B_, NT>>>(images, apply_u, flip_u, brightness_u,
                             contrast_u, saturation_u, top_idx, left_idx, out);
}

// round 15
// speedup vs baseline: 1.3596x; 1.3596x over previous
#include <cuda_runtime.h>
#include <cstdint>

// Problem constants: B=128, C=3, H=W=256, PROB=0.9, BRI=CON=SAT=0.2, CUT=0.25 -> CH=CW=64.
#define PROB_ 0.9f
static constexpr int B_     = 128;
static constexpr int H_     = 256;
static constexpr int W_     = 256;
static constexpr int CH_    = 64;
static constexpr int CW_    = 64;
static constexpr int PLANE  = H_ * W_;        // 65536 floats
static constexpr int PLANE4 = PLANE / 4;      // 16384 float4
static constexpr int CLUS   = 4;              // CTAs per batch (cluster)
static constexpr int NT     = 1024;           // threads per CTA
static constexpr int Q4     = PLANE4 / CLUS;  // 4096 float4 per channel slice (64 rows)
static constexpr int ITQ    = Q4 / NT;        // 4 float4 per thread per channel
static constexpr int SMEM_BYTES = 3 * Q4 * 16 + 128;  // 3 channel tiles + aux

// ---------------------------------------------------------------------------
// One 4-CTA cluster = one batch; each CTA owns 64 rows x 3 channels (192KB) in
// SMEM. Input is read from DRAM exactly once (3 staged cp.async groups; the
// per-channel reduction of tile k overlaps the in-flight loads of k+1..).
// Plane-mean partials are exchanged across the cluster via 12 PARALLEL DSMEM
// reads (one (rank, channel) pair per thread, no atomics); the transform runs
// out of SMEM and streams output to DRAM with default-policy stores (R12
// falsified __stcs: evict-first hints degrade write-drain efficiency).
//
// Algebra: out_ch = A*x0_ch + D*g0 + E_ch with
//   A = s*b*c ; D = (1-s)*b*c ; g0 = mean_ch(x0 pixel)
//   E_ch = (1-c)*(s*M_ch + (1-s)*Mbar),  M_ch = b*mean(raw plane ch)
// flip preserves plane means; cutout and apply are selects.
// ---------------------------------------------------------------------------
__global__ void __cluster_dims__(CLUS, 1, 1) __launch_bounds__(NT, 1)
aug_kernel(const float* __restrict__ img,
           const float* __restrict__ apply_u,
           const float* __restrict__ flip_u,
           const float* __restrict__ bri_u,
           const float* __restrict__ con_u,
           const float* __restrict__ sat_u,
           const int*   __restrict__ top_idx,
           const int*   __restrict__ left_idx,
           float* __restrict__ out)
{
    extern __shared__ float4 smem4[];                   // 3 * Q4 float4 tiles
    float* aux = reinterpret_cast<float*>(smem4 + 3 * Q4);
    // aux[0..2]  = this CTA's partial channel sums (read remotely by siblings)
    // aux[8..19] = gathered partials: aux[8 + r*3 + ch] from rank r, channel ch

    const int tid  = threadIdx.x;
    const int b    = blockIdx.x >> 2;
    const int rank = blockIdx.x & 3;

    // Slice base (float4 units): batch base + rank's 64-row band of channel 0.
    const size_t base4 = (size_t)b * 3 * PLANE4 + (size_t)rank * Q4;
    const float4* in0 = reinterpret_cast<const float4*>(img) + base4;
    const float4* in1 = in0 + PLANE4;
    const float4* in2 = in0 + 2 * PLANE4;
    float4* out0 = reinterpret_cast<float4*>(out) + base4;
    float4* out1 = out0 + PLANE4;
    float4* out2 = out0 + 2 * PLANE4;

    const bool apply = (__ldg(apply_u + b) < PROB_);
    if (!apply) {
        // Whole cluster takes this path (same batch) -> no barrier mismatch.
#pragma unroll
        for (int i = 0; i < ITQ; i++) {
            const int j = tid + i * NT;
            out0[j] = __ldg(in0 + j);
            out1[j] = __ldg(in1 + j);
            out2[j] = __ldg(in2 + j);
        }
        return;
    }

    // ---------------- Phase 1: staged GMEM -> SMEM + overlapped sums -------
    const uint32_t sbase = (uint32_t)__cvta_generic_to_shared(smem4);
#pragma unroll
    for (int ch = 0; ch < 3; ch++) {
        const float4* src = (ch == 0) ? in0 : (ch == 1) ? in1 : in2;
#pragma unroll
        for (int i = 0; i < ITQ; i++) {
            const int j = tid + i * NT;
            const uint32_t dst = sbase + (uint32_t)(ch * Q4 + j) * 16u;
            asm volatile("cp.async.cg.shared.global [%0], [%1], 16;\n"
                         :: "r"(dst), "l"(src + j));
        }
        asm volatile("cp.async.commit_group;\n");
    }

    // Sum channel k while channels k+1.. are still loading. Each thread sums
    // exactly the elements it issued, so only its own group completion is
    // needed (no barrier until the block reduce).
    float s0, s1, s2;
    {
        auto sum_ch = [&](int ch) -> float {
            float s = 0.0f;
#pragma unroll
            for (int i = 0; i < ITQ; i++) {
                const int j = tid + i * NT;
                float4 v = smem4[ch * Q4 + j];
                s += (v.x + v.y) + (v.z + v.w);
            }
            return s;
        };
        asm volatile("cp.async.wait_group 2;\n" ::: "memory");
        s0 = sum_ch(0);
        asm volatile("cp.async.wait_group 1;\n" ::: "memory");
        s1 = sum_ch(1);
        asm volatile("cp.async.wait_group 0;\n" ::: "memory");
        s2 = sum_ch(2);
    }

#pragma unroll
    for (int o = 16; o > 0; o >>= 1) {
        s0 += __shfl_xor_sync(0xFFFFFFFFu, s0, o);
        s1 += __shfl_xor_sync(0xFFFFFFFFu, s1, o);
        s2 += __shfl_xor_sync(0xFFFFFFFFu, s2, o);
    }
    __shared__ float smA[32], smB[32], smC[32];
    const int wid = tid >> 5;
    if ((tid & 31) == 0) { smA[wid] = s0; smB[wid] = s1; smC[wid] = s2; }
    __syncthreads();   // also publishes all SMEM tiles for the flip reads
    if (tid < 32) {
        float a = smA[tid], d = smB[tid], e = smC[tid];
#pragma unroll
        for (int o = 16; o > 0; o >>= 1) {
            a += __shfl_xor_sync(0xFFFFFFFFu, a, o);
            d += __shfl_xor_sync(0xFFFFFFFFu, d, o);
            e += __shfl_xor_sync(0xFFFFFFFFu, e, o);
        }
        if (tid == 0) { aux[0] = a; aux[1] = d; aux[2] = e; }
    }
    __syncthreads();

    // ---------------- Cluster-wide sum exchange: 12 parallel DSMEM reads ---
    asm volatile("barrier.cluster.arrive.aligned;" ::: "memory");
    asm volatile("barrier.cluster.wait.aligned;" ::: "memory");

    if (tid < 12) {
        const int ch = tid % 3;
        const int r  = tid / 3;
        uint32_t la = (uint32_t)__cvta_generic_to_shared(&aux[ch]);
        uint32_t ra;
        asm volatile("mapa.shared::cluster.u32 %0, %1, %2;"
                     : "=r"(ra) : "r"(la), "r"(r));
        float v;
        asm volatile("ld.shared::cluster.f32 %0, [%1];" : "=f"(v) : "r"(ra));
        aux[8 + tid] = v;   // [8 + r*3 + ch]
    }
    __syncthreads();

    // Signal "done reading sibling SMEM"; matching wait is at kernel end so
    // siblings' reads of OUR aux[] complete before this CTA's SMEM retires.
    asm volatile("barrier.cluster.arrive.aligned;" ::: "memory");

    // ---------------- Per-batch constants -----------------------------------
    const float bv = 0.8f + 0.4f * __ldg(bri_u + b);
    const float cv = 0.8f + 0.4f * __ldg(con_u + b);
    const float sv = 0.8f + 0.4f * __ldg(sat_u + b);

    const float inv = 1.0f / (float)PLANE;
    const float M0 = (aux[8]  + aux[11] + aux[14] + aux[17]) * inv * bv;
    const float M1 = (aux[9]  + aux[12] + aux[15] + aux[18]) * inv * bv;
    const float M2 = (aux[10] + aux[13] + aux[16] + aux[19]) * inv * bv;
    const float Mbar = (M0 + M1 + M2) * (1.0f / 3.0f);

    const float A  = sv * bv * cv;
    const float D  = (1.0f - sv) * bv * cv;
    const float k  = 1.0f - cv;
    const float os = 1.0f - sv;
    const float E0 = k * (sv * M0 + os * Mbar);
    const float E1 = k * (sv * M1 + os * Mbar);
    const float E2 = k * (sv * M2 + os * Mbar);

    const bool flip = (__ldg(flip_u + b) < 0.5f);
    const int  t_   = __ldg(top_idx + b);
    const int  l_   = __ldg(left_idx + b);

    // ---------------- Phase 2: transform from SMEM, stream to DRAM ---------
#pragma unroll
    for (int i = 0; i < ITQ; i++) {
        const int j  = tid + i * NT;        // float4 idx within 64x64-f4 slice
        const int rr = j >> 6;              // local row 0..63
        const int wg = j & 63;              // output float4 column group
        const int h  = rank * 64 + rr;      // global row
        const int sj = flip ? ((rr << 6) | (63 - wg)) : j;

        float4 r = smem4[sj];
        float4 g = smem4[Q4 + sj];
        float4 c = smem4[2 * Q4 + sj];
        if (flip) {
            float t;
            t = r.x; r.x = r.w; r.w = t;  t = r.y; r.y = r.z; r.z = t;
            t = g.x; g.x = g.w; g.w = t;  t = g.y; g.y = g.z; g.z = t;
            t = c.x; c.x = c.w; c.w = t;  t = c.y; c.y = c.z; c.z = t;
        }

        const bool row_in = (h >= t_) && (h < t_ + CH_);
        const int  w0 = wg << 2;

        float4 oR, oG, oB;
        float gray; bool cut; int col;

        col = w0 + 0; cut = row_in && (col >= l_) && (col < l_ + CW_);
        gray = (r.x + g.x + c.x) * (1.0f / 3.0f);
        oR.x = cut ? 0.0f : fmaf(A, r.x, fmaf(D, gray, E0));
        oG.x = cut ? 0.0f : fmaf(A, g.x, fmaf(D, gray, E1));
        oB.x = cut ? 0.0f : fmaf(A, c.x, fmaf(D, gray, E2));

        col = w0 + 1; cut = row_in && (col >= l_) && (col < l_ + CW_);
        gray = (r.y + g.y + c.y) * (1.0f / 3.0f);
        oR.y = cut ? 0.0f : fmaf(A, r.y, fmaf(D, gray, E0));
        oG.y = cut ? 0.0f : fmaf(A, g.y, fmaf(D, gray, E1));
        oB.y = cut ? 0.0f : fmaf(A, c.y, fmaf(D, gray, E2));

        col = w0 + 2; cut = row_in && (col >= l_) && (col < l_ + CW_);
        gray = (r.z + g.z + c.z) * (1.0f / 3.0f);
        oR.z = cut ? 0.0f : fmaf(A, r.z, fmaf(D, gray, E0));
        oG.z = cut ? 0.0f : fmaf(A, g.z, fmaf(D, gray, E1));
        oB.z = cut ? 0.0f : fmaf(A, c.z, fmaf(D, gray, E2));

        col = w0 + 3; cut = row_in && (col >= l_) && (col < l_ + CW_);
        gray = (r.w + g.w + c.w) * (1.0f / 3.0f);
        oR.w = cut ? 0.0f : fmaf(A, r.w, fmaf(D, gray, E0));
        oG.w = cut ? 0.0f : fmaf(A, g.w, fmaf(D, gray, E1));
        oB.w = cut ? 0.0f : fmaf(A, c.w, fmaf(D, gray, E2));

        out0[j] = oR;
        out1[j] = oG;
        out2[j] = oB;
    }

    asm volatile("barrier.cluster.wait.aligned;" ::: "memory");
}

extern "C" void kernel_launch(void* const* d_in, const int* in_sizes, int n_in,
                              void* d_out, int out_size) {
    const float* images       = (const float*)d_in[0];
    const float* apply_u      = (const float*)d_in[1];
    const float* flip_u       = (const float*)d_in[2];
    const float* brightness_u = (const float*)d_in[3];
    const float* contrast_u   = (const float*)d_in[4];
    const float* saturation_u = (const float*)d_in[5];
    const int*   top_idx      = (const int*)d_in[6];
    const int*   left_idx     = (const int*)d_in[7];
    float* out = (float*)d_out;

    cudaFuncSetAttribute(aug_kernel,
                         cudaFuncAttributeMaxDynamicSharedMemorySize,
                         SMEM_BYTES);

    aug_kernel<<<B_ * CLUS, NT, SMEM_BYTES>>>(
        images, apply_u, flip_u, brightness_u, contrast_u, saturation_u,
        top_idx, left_idx, out);
}